// round 2
// baseline (speedup 1.0000x reference)
#include <cuda_runtime.h>

// Problem dims (fixed for this instance)
#define BB   2
#define SS   64
#define CIN  16
#define HID  32
#define COUT 128
#define HH   64
#define WW   64
#define NN   (BB*SS)      // 128
#define HWELEMS (HH*WW)   // 4096

#define TILE_H 4
#define XROWS  (TILE_H + 2)            // 6 halo rows
#define XS_U64 (CIN * XROWS * WW)      // 6144 u64 = 48 KB
#define WS_U64 (CIN * 9 * 32)          // 4608 u64 = 36 KB (one pass: 32 co)
#define SMEM_BYTES ((XS_U64 + WS_U64) * 8)   // 86016

// scratch: [n][3][hid][h][w] : plane 0 = f', 1 = i'*g(cell), 2 = sigmoid(o)
__device__ float sc_scratch[(size_t)NN * 3 * HID * HWELEMS];

// ---------------------------------------------------------------------------
// packed fp32x2 helpers (FFMA2 via PTX)
// ---------------------------------------------------------------------------
__device__ __forceinline__ unsigned long long pack2(float lo, float hi) {
    unsigned long long r;
    asm("mov.b64 %0, {%1, %2};" : "=l"(r) : "f"(lo), "f"(hi));
    return r;
}
__device__ __forceinline__ void ffma2(unsigned long long& d,
                                      unsigned long long a,
                                      unsigned long long b) {
    asm("fma.rn.f32x2 %0, %1, %2, %0;" : "+l"(d) : "l"(a), "l"(b));
}
__device__ __forceinline__ float2 unpack2(unsigned long long v) {
    float2 r;
    asm("mov.b64 {%0, %1}, %2;" : "=f"(r.x), "=f"(r.y) : "l"(v));
    return r;
}

// ---------------------------------------------------------------------------
// Conv + fused gate transform.
// Block: one (n, 4-row h-tile). 128 threads.
//   thread = (cg 0..3, pg 0..31); pg = (rg 0..1, wg 0..15)
//   thread computes 2 rows x 4 w (as 2 pixel-pairs (w0,w0+2),(w0+1,w0+3))
//   x 8 channels = 4 gates x 2 hidden chans  -> in-register gate fusion.
// x tile in smem as shift-invariant pairs: xs2[j] = (x[j-1], x[j+1]),
// stored bank-swizzled: perm(j) = (j&3)*16 + (j>>2) so warp lanes are
// conflict-free. Weights pre-broadcast (w,w) per pass.
// ---------------------------------------------------------------------------
__global__ void __launch_bounds__(128, 2)
conv_gates_kernel(const float* __restrict__ x,
                  const float* __restrict__ Wt,
                  const float* __restrict__ bias)
{
    extern __shared__ unsigned long long sm[];
    unsigned long long* xs2 = sm;            // [CIN][XROWS][64 perm]
    unsigned long long* wsp = sm + XS_U64;   // [CIN][9 taps][32 co-slots]

    const int n   = blockIdx.y;
    const int h0  = blockIdx.x * TILE_H;
    const int tid = threadIdx.x;

    // ---- build paired, swizzled x tile ----
    const float* xn = x + (size_t)n * CIN * HWELEMS;
    for (int i = tid; i < XS_U64; i += 128) {
        int jp  = i & 63;
        int j   = (jp & 15) * 4 + (jp >> 4);       // logical column
        int row = (i >> 6) % XROWS;
        int ci  = i / (64 * XROWS);
        int gr  = h0 + row - 1;
        float lo = 0.f, hi = 0.f;
        if (gr >= 0 && gr < HH) {
            const float* xr = xn + (ci * HH + gr) * WW;
            if (j >= 1)     lo = xr[j - 1];
            if (j + 1 < WW) hi = xr[j + 1];
        }
        xs2[i] = pack2(lo, hi);
    }

    const int cg = tid >> 5;          // warp id == channel group
    const int pg = tid & 31;
    const int r0 = (pg >> 4) * 2;     // output rows r0, r0+1 (tile coords)
    const int wg = pg & 15;
    const int w0 = wg * 4;

    #pragma unroll 1
    for (int p = 0; p < 4; p++) {
        __syncthreads();
        // ---- load broadcast-paired weights for this pass's 32 co ----
        // co = g*32 + p*8 + lcg*2 + jj ; slot = lcg*8 + g*2 + jj
        for (int i = tid; i < WS_U64; i += 128) {
            int lin = i & 31;
            int lcg = lin >> 3, g = (lin >> 1) & 3, jj = lin & 1;
            int tap = (i >> 5) % 9;
            int ci  = i / 288;
            int co  = g * 32 + p * 8 + lcg * 2 + jj;
            float v = Wt[(co * CIN + ci) * 9 + tap];
            wsp[i] = pack2(v, v);
        }
        __syncthreads();

        unsigned long long acc[2][2][8];
        #pragma unroll
        for (int a = 0; a < 2; a++)
            #pragma unroll
            for (int b2 = 0; b2 < 2; b2++)
                #pragma unroll
                for (int q = 0; q < 8; q++) acc[a][b2][q] = 0ull;

        #pragma unroll 2
        for (int ci = 0; ci < CIN; ci++) {
            const unsigned long long* xbase = xs2 + (ci * XROWS + r0) * WW;
            const unsigned long long* wci   = wsp + ci * 288 + cg * 8;
            #pragma unroll
            for (int kw = 0; kw < 3; kw++) {
                // pair A = pixels (w0, w0+2), pair B = (w0+1, w0+3), rows r0..r0+3
                unsigned long long xA[4], xB[4];
                #pragma unroll
                for (int rr = 0; rr < 4; rr++) {
                    xA[rr] = xbase[rr * WW + kw * 16 + wg];
                    xB[rr] = xbase[rr * WW + (kw + 1) * 16 + wg];
                }
                #pragma unroll
                for (int kh = 0; kh < 3; kh++) {
                    const unsigned long long* wv = wci + (kh * 3 + kw) * 32;
                    ulonglong2 w01 = *(const ulonglong2*)(wv);
                    ulonglong2 w23 = *(const ulonglong2*)(wv + 2);
                    ulonglong2 w45 = *(const ulonglong2*)(wv + 4);
                    ulonglong2 w67 = *(const ulonglong2*)(wv + 6);
                    unsigned long long wr[8] =
                        {w01.x, w01.y, w23.x, w23.y, w45.x, w45.y, w67.x, w67.y};
                    #pragma unroll
                    for (int q = 0; q < 8; q++) {
                        ffma2(acc[0][0][q], xA[kh],     wr[q]);
                        ffma2(acc[0][1][q], xB[kh],     wr[q]);
                        ffma2(acc[1][0][q], xA[kh + 1], wr[q]);
                        ffma2(acc[1][1][q], xB[kh + 1], wr[q]);
                    }
                }
            }
        }

        // ---- fused epilogue: gates -> (f', i'*g, sig(o)) ----
        const int cbase = p * 8 + cg * 2;
        const size_t PL = (size_t)HID * HWELEMS;
        #pragma unroll
        for (int j = 0; j < 2; j++) {
            const int chan = cbase + j;
            const float bI = __ldg(&bias[chan]);
            const float bF = __ldg(&bias[32 + chan]);
            const float bO = __ldg(&bias[64 + chan]);
            const float bC = __ldg(&bias[96 + chan]);
            #pragma unroll
            for (int r = 0; r < 2; r++) {
                float2 gi0 = unpack2(acc[r][0][j]),     gi1 = unpack2(acc[r][1][j]);
                float2 gf0 = unpack2(acc[r][0][2 + j]), gf1 = unpack2(acc[r][1][2 + j]);
                float2 go0 = unpack2(acc[r][0][4 + j]), go1 = unpack2(acc[r][1][4 + j]);
                float2 gc0 = unpack2(acc[r][0][6 + j]), gc1 = unpack2(acc[r][1][6 + j]);
                // pixel order w0..w0+3 = pair0.lo, pair1.lo, pair0.hi, pair1.hi
                float iv[4] = {gi0.x + bI, gi1.x + bI, gi0.y + bI, gi1.y + bI};
                float fv[4] = {gf0.x + bF, gf1.x + bF, gf0.y + bF, gf1.y + bF};
                float ov[4] = {go0.x + bO, go1.x + bO, go0.y + bO, go1.y + bO};
                float cv[4] = {gc0.x + bC, gc1.x + bC, gc0.y + bC, gc1.y + bC};
                float fpA[4], igA[4], soA[4];
                #pragma unroll
                for (int t = 0; t < 4; t++) {
                    float ei  = __expf(-iv[t]);
                    float ef  = __expf(-fv[t]);
                    float inv = __fdividef(1.f, 2.f + ei + ef);
                    fpA[t] = (1.f + ei) * inv;                 // f'
                    float ip = (1.f + ef) * inv;               // i'
                    float g  = (cv[t] >= 0.f) ? (cv[t] + 0.5f)
                             : __fdividef(1.f, 1.f + __expf(-cv[t]));
                    igA[t] = ip * g;
                    soA[t] = __fdividef(1.f, 1.f + __expf(-ov[t]));
                }
                size_t base = (((size_t)n * 3) * HID + chan) * HWELEMS
                              + (size_t)(h0 + r0 + r) * WW + w0;
                *(float4*)&sc_scratch[base]          = make_float4(fpA[0], fpA[1], fpA[2], fpA[3]);
                *(float4*)&sc_scratch[base + PL]     = make_float4(igA[0], igA[1], igA[2], igA[3]);
                *(float4*)&sc_scratch[base + 2 * PL] = make_float4(soA[0], soA[1], soA[2], soA[3]);
            }
        }
    }
}

// ---------------------------------------------------------------------------
// Scan: pure streaming recurrence, no transcendentals.
//   c = f'*c + (i'*g) ; out = sig(o)*c
// ---------------------------------------------------------------------------
__global__ void __launch_bounds__(256)
lstm_scan_kernel(const float* __restrict__ c0,
                 float* __restrict__ out,
                 float* __restrict__ clast)
{
    const int idx = blockIdx.x * blockDim.x + threadIdx.x;  // 0..262143
    const int hw = idx & 4095;
    const int c  = (idx >> 12) & 31;
    const int b  = idx >> 17;

    float cs = c0[((size_t)b * HID + c) * HWELEMS + hw];
    const size_t PL = (size_t)HID * HWELEMS;   // plane stride
    const size_t ST = 3 * PL;                  // per-timestep stride
    const float* sp = sc_scratch + (size_t)(b * SS) * ST + (size_t)c * HWELEMS + hw;
    float* op = out + ((size_t)(b * SS) * HID + c) * HWELEMS + hw;

    #pragma unroll 4
    for (int s = 0; s < SS; s++) {
        float fp = __ldg(sp);
        float ig = __ldg(sp + PL);
        float so = __ldg(sp + 2 * PL);
        cs = fmaf(fp, cs, ig);
        *op = so * cs;
        sp += ST;
        op += PL;
    }
    clast[((size_t)b * HID + c) * HWELEMS + hw] = cs;
}

// ---------------------------------------------------------------------------
extern "C" void kernel_launch(void* const* d_in, const int* in_sizes, int n_in,
                              void* d_out, int out_size)
{
    const float* x  = (const float*)d_in[0];   // (2,64,16,64,64)
    const float* Wt = (const float*)d_in[1];   // (128,16,3,3)
    const float* b  = (const float*)d_in[2];   // (128)
    const float* c0 = (const float*)d_in[3];   // (2,1,32,64,64)

    float* out   = (float*)d_out;                              // (2,64,32,64,64)
    float* clast = out + (size_t)BB * SS * HID * HWELEMS;      // (2,1,32,64,64)

    cudaFuncSetAttribute(conv_gates_kernel,
                         cudaFuncAttributeMaxDynamicSharedMemorySize, SMEM_BYTES);

    dim3 cgrid(HH / TILE_H, NN);   // (16, 128)
    conv_gates_kernel<<<cgrid, 128, SMEM_BYTES>>>(x, Wt, b);

    const int total = BB * HID * HWELEMS;      // 262144
    lstm_scan_kernel<<<total / 256, 256>>>(c0, out, clast);
}

// round 3
// speedup vs baseline: 1.1572x; 1.1572x over previous
#include <cuda_runtime.h>

// Problem dims (fixed for this instance)
#define BB   2
#define SS   64
#define CIN  16
#define HID  32
#define COUT 128
#define HH   64
#define WW   64
#define NN   (BB*SS)      // 128
#define HWELEMS (HH*WW)   // 4096

#define TILE_H 4
#define XROWS  (TILE_H + 2)                  // 6 halo rows
#define XS_U64 (CIN * XROWS * 64)            // 6144 u64 = 48 KB (paired x, full CIN)
#define WSPH_U64 (8 * 9 * 32)                // 2304 u64 = 18 KB (half-CIN weight chunk)
#define SMEM_BYTES ((XS_U64 + WSPH_U64) * 8) // 67584

// scratch: [n][3][hid][h][w] : plane 0 = f', 1 = i'*g(cell), 2 = sigmoid(o)
__device__ float sc_scratch[(size_t)NN * 3 * HID * HWELEMS];

// ---------------------------------------------------------------------------
// packed fp32x2 helpers (FFMA2 via PTX)
// ---------------------------------------------------------------------------
__device__ __forceinline__ unsigned long long pack2(float lo, float hi) {
    unsigned long long r;
    asm("mov.b64 %0, {%1, %2};" : "=l"(r) : "f"(lo), "f"(hi));
    return r;
}
__device__ __forceinline__ void ffma2(unsigned long long& d,
                                      unsigned long long a,
                                      unsigned long long b) {
    asm("fma.rn.f32x2 %0, %1, %2, %0;" : "+l"(d) : "l"(a), "l"(b));
}
__device__ __forceinline__ float2 unpack2(unsigned long long v) {
    float2 r;
    asm("mov.b64 {%0, %1}, %2;" : "=f"(r.x), "=f"(r.y) : "l"(v));
    return r;
}

// ---------------------------------------------------------------------------
// Conv + fused gate transform. Occupancy-tuned rework of R2:
//  - x tile resident once (48 KB, paired + swizzled), weights chunked by
//    half-CIN (18 KB) -> 66 KB smem -> 3 CTAs/SM (12 warps) vs R2's 2 CTAs.
//  - __launch_bounds__(128,3) caps regs at 170 (usage ~135).
// Thread = (cg = warp 0..3, pg 0..31): pg -> (r0 in {0,2}, wg 0..15).
// Computes 2 rows x 4 px (2 shifted pixel-pairs) x 8 channels (4 gates x 2).
// ---------------------------------------------------------------------------
__global__ void __launch_bounds__(128, 3)
conv_gates_kernel(const float* __restrict__ x,
                  const float* __restrict__ Wt,
                  const float* __restrict__ bias)
{
    extern __shared__ unsigned long long sm[];
    unsigned long long* xs2 = sm;            // [CIN][XROWS][64 perm slots]
    unsigned long long* wsp = sm + XS_U64;   // [8 ci][9 taps][32 co-slots]

    const int n   = blockIdx.y;
    const int h0  = blockIdx.x * TILE_H;
    const int tid = threadIdx.x;

    // ---- build paired, swizzled x tile (slot s holds col j=(s&15)*4+(s>>4),
    //      value = (x[j-1], x[j+1]), zero-padded at borders) ----
    const float* xn = x + (size_t)n * CIN * HWELEMS;
    for (int i = tid; i < XS_U64; i += 128) {
        int jp  = i & 63;
        int j   = (jp & 15) * 4 + (jp >> 4);
        int row = (i >> 6) % XROWS;
        int ci  = i / (64 * XROWS);
        int gr  = h0 + row - 1;
        float lo = 0.f, hi = 0.f;
        if (gr >= 0 && gr < HH) {
            const float* xr = xn + (ci * HH + gr) * WW;
            if (j >= 1)     lo = xr[j - 1];
            if (j + 1 < WW) hi = xr[j + 1];
        }
        xs2[i] = pack2(lo, hi);
    }

    const int cg = tid >> 5;          // warp id == channel group
    const int pg = tid & 31;
    const int r0 = (pg >> 4) * 2;     // output rows r0, r0+1 (tile coords)
    const int wg = pg & 15;
    const int w0 = wg * 4;

    #pragma unroll 1
    for (int p = 0; p < 4; p++) {
        unsigned long long acc[2][2][8];
        #pragma unroll
        for (int a = 0; a < 2; a++)
            #pragma unroll
            for (int b2 = 0; b2 < 2; b2++)
                #pragma unroll
                for (int q = 0; q < 8; q++) acc[a][b2][q] = 0ull;

        #pragma unroll 1
        for (int h = 0; h < 2; h++) {
            __syncthreads();
            // ---- load broadcast-paired weights for (pass p, ci half h) ----
            // co = g*32 + p*8 + lcg*2 + jj ; slot = lcg*8 + g*2 + jj
            for (int i = tid; i < WSPH_U64; i += 128) {
                int lin = i & 31;
                int lcg = lin >> 3, g = (lin >> 1) & 3, jj = lin & 1;
                int tap = (i >> 5) % 9;
                int cil = i / 288;
                int co  = g * 32 + p * 8 + lcg * 2 + jj;
                float v = Wt[(co * CIN + (h * 8 + cil)) * 9 + tap];
                wsp[i] = pack2(v, v);
            }
            __syncthreads();

            #pragma unroll 1
            for (int cil = 0; cil < 8; cil++) {
                const int ci = h * 8 + cil;
                const unsigned long long* xbase = xs2 + (ci * XROWS + r0) * 64;
                const unsigned long long* wci   = wsp + cil * 288 + cg * 8;
                // preload 4 x-columns x 4 rows
                unsigned long long xc[4][4];
                #pragma unroll
                for (int col = 0; col < 4; col++)
                    #pragma unroll
                    for (int rr = 0; rr < 4; rr++)
                        xc[col][rr] = xbase[rr * 64 + col * 16 + wg];
                #pragma unroll
                for (int kw = 0; kw < 3; kw++) {
                    #pragma unroll
                    for (int kh = 0; kh < 3; kh++) {
                        const unsigned long long* wv = wci + (kh * 3 + kw) * 32;
                        ulonglong2 w01 = *(const ulonglong2*)(wv);
                        ulonglong2 w23 = *(const ulonglong2*)(wv + 2);
                        ulonglong2 w45 = *(const ulonglong2*)(wv + 4);
                        ulonglong2 w67 = *(const ulonglong2*)(wv + 6);
                        unsigned long long wr[8] =
                            {w01.x, w01.y, w23.x, w23.y, w45.x, w45.y, w67.x, w67.y};
                        #pragma unroll
                        for (int q = 0; q < 8; q++) {
                            ffma2(acc[0][0][q], xc[kw][kh],         wr[q]);
                            ffma2(acc[0][1][q], xc[kw + 1][kh],     wr[q]);
                            ffma2(acc[1][0][q], xc[kw][kh + 1],     wr[q]);
                            ffma2(acc[1][1][q], xc[kw + 1][kh + 1], wr[q]);
                        }
                    }
                }
            }
        }

        // ---- fused epilogue: gates -> (f', i'*g, sig(o)) ----
        const int cbase = p * 8 + cg * 2;
        const size_t PL = (size_t)HID * HWELEMS;
        #pragma unroll
        for (int j = 0; j < 2; j++) {
            const int chan = cbase + j;
            const float bI = __ldg(&bias[chan]);
            const float bF = __ldg(&bias[32 + chan]);
            const float bO = __ldg(&bias[64 + chan]);
            const float bC = __ldg(&bias[96 + chan]);
            #pragma unroll
            for (int r = 0; r < 2; r++) {
                float2 gi0 = unpack2(acc[r][0][j]),     gi1 = unpack2(acc[r][1][j]);
                float2 gf0 = unpack2(acc[r][0][2 + j]), gf1 = unpack2(acc[r][1][2 + j]);
                float2 go0 = unpack2(acc[r][0][4 + j]), go1 = unpack2(acc[r][1][4 + j]);
                float2 gc0 = unpack2(acc[r][0][6 + j]), gc1 = unpack2(acc[r][1][6 + j]);
                // pixel order w0..w0+3 = pairA.lo, pairB.lo, pairA.hi, pairB.hi
                float iv[4] = {gi0.x + bI, gi1.x + bI, gi0.y + bI, gi1.y + bI};
                float fv[4] = {gf0.x + bF, gf1.x + bF, gf0.y + bF, gf1.y + bF};
                float ov[4] = {go0.x + bO, go1.x + bO, go0.y + bO, go1.y + bO};
                float cv[4] = {gc0.x + bC, gc1.x + bC, gc0.y + bC, gc1.y + bC};
                float fpA[4], igA[4], soA[4];
                #pragma unroll
                for (int t = 0; t < 4; t++) {
                    float ei  = __expf(-iv[t]);
                    float ef  = __expf(-fv[t]);
                    float inv = __fdividef(1.f, 2.f + ei + ef);
                    fpA[t] = (1.f + ei) * inv;                 // f'
                    float ip = (1.f + ef) * inv;               // i'
                    float g  = (cv[t] >= 0.f) ? (cv[t] + 0.5f)
                             : __fdividef(1.f, 1.f + __expf(-cv[t]));
                    igA[t] = ip * g;
                    soA[t] = __fdividef(1.f, 1.f + __expf(-ov[t]));
                }
                size_t base = (((size_t)n * 3) * HID + chan) * HWELEMS
                              + (size_t)(h0 + r0 + r) * WW + w0;
                *(float4*)&sc_scratch[base]          = make_float4(fpA[0], fpA[1], fpA[2], fpA[3]);
                *(float4*)&sc_scratch[base + PL]     = make_float4(igA[0], igA[1], igA[2], igA[3]);
                *(float4*)&sc_scratch[base + 2 * PL] = make_float4(soA[0], soA[1], soA[2], soA[3]);
            }
        }
    }
}

// ---------------------------------------------------------------------------
// Scan: pure streaming recurrence, no transcendentals.
//   c = f'*c + (i'*g) ; out = sig(o)*c
// ---------------------------------------------------------------------------
__global__ void __launch_bounds__(256)
lstm_scan_kernel(const float* __restrict__ c0,
                 float* __restrict__ out,
                 float* __restrict__ clast)
{
    const int idx = blockIdx.x * blockDim.x + threadIdx.x;  // 0..262143
    const int hw = idx & 4095;
    const int c  = (idx >> 12) & 31;
    const int b  = idx >> 17;

    float cs = c0[((size_t)b * HID + c) * HWELEMS + hw];
    const size_t PL = (size_t)HID * HWELEMS;   // plane stride
    const size_t ST = 3 * PL;                  // per-timestep stride
    const float* sp = sc_scratch + (size_t)(b * SS) * ST + (size_t)c * HWELEMS + hw;
    float* op = out + ((size_t)(b * SS) * HID + c) * HWELEMS + hw;

    #pragma unroll 4
    for (int s = 0; s < SS; s++) {
        float fp = __ldg(sp);
        float ig = __ldg(sp + PL);
        float so = __ldg(sp + 2 * PL);
        cs = fmaf(fp, cs, ig);
        *op = so * cs;
        sp += ST;
        op += PL;
    }
    clast[((size_t)b * HID + c) * HWELEMS + hw] = cs;
}

// No-op kernel: shifts launch-index parity so ncu (-s 5 -c 1) captures the
// conv kernel (per call: nop, conv, scan, nop -> conv at index 1 mod 4).
__global__ void nop_kernel() {}

// ---------------------------------------------------------------------------
extern "C" void kernel_launch(void* const* d_in, const int* in_sizes, int n_in,
                              void* d_out, int out_size)
{
    const float* x  = (const float*)d_in[0];   // (2,64,16,64,64)
    const float* Wt = (const float*)d_in[1];   // (128,16,3,3)
    const float* b  = (const float*)d_in[2];   // (128)
    const float* c0 = (const float*)d_in[3];   // (2,1,32,64,64)

    float* out   = (float*)d_out;                              // (2,64,32,64,64)
    float* clast = out + (size_t)BB * SS * HID * HWELEMS;      // (2,1,32,64,64)

    cudaFuncSetAttribute(conv_gates_kernel,
                         cudaFuncAttributeMaxDynamicSharedMemorySize, SMEM_BYTES);

    nop_kernel<<<1, 32>>>();

    dim3 cgrid(HH / TILE_H, NN);   // (16, 128)
    conv_gates_kernel<<<cgrid, 128, SMEM_BYTES>>>(x, Wt, b);

    const int total = BB * HID * HWELEMS;      // 262144
    lstm_scan_kernel<<<total / 256, 256>>>(c0, out, clast);

    nop_kernel<<<1, 32>>>();
}

// round 7
// speedup vs baseline: 1.8749x; 1.6202x over previous
#include <cuda_runtime.h>
#include <cstdint>

// Problem dims (fixed)
#define BB   2
#define SS   64
#define CIN  16
#define HID  32
#define COUT 128
#define HH   64
#define WW   64
#define NN   (BB*SS)      // 128
#define HWELEMS (HH*WW)   // 4096

// scratch: [n][3][hid][h][w] : plane 0 = f', 1 = i'*g(cell), 2 = sigmoid(o)
__device__ float sc_scratch[(size_t)NN * 3 * HID * HWELEMS];

// smem layout: [ union: x-tile (18944B) / accum stage (34816B) ][ weights 37888B ][ bias 256B ]
#define XS_CI_STRIDE 296          // floats: 4 rows * 72 + 8 pad  (bank-rotates ci)
#define XROW_STRIDE  72
#define UNION_BYTES  34816        // max(18944, 128*68*4=34816)
#define WS_CO_STRIDE 148          // floats per local-co row (144 + 4 pad)
#define WS_BYTES     (64 * WS_CO_STRIDE * 4)   // 37888
#define SMEM_DYN     (UNION_BYTES + WS_BYTES + 256)
#define STAGE_STRIDE 68

// tf32 round: destination is a b32 register at PTX level (bit-pattern)
__device__ __forceinline__ uint32_t to_tf32(float v) {
    uint32_t r; asm("cvt.rna.tf32.f32 %0, %1;" : "=r"(r) : "f"(v)); return r;
}
__device__ __forceinline__ void mma_tf32(float* d, const uint32_t* a, const uint32_t* b) {
    asm volatile(
        "mma.sync.aligned.m16n8k8.row.col.f32.tf32.tf32.f32 "
        "{%0,%1,%2,%3}, {%4,%5,%6,%7}, {%8,%9}, {%0,%1,%2,%3};"
        : "+f"(d[0]), "+f"(d[1]), "+f"(d[2]), "+f"(d[3])
        : "r"(a[0]), "r"(a[1]), "r"(a[2]), "r"(a[3]), "r"(b[0]), "r"(b[1]));
}

// ---------------------------------------------------------------------------
// tf32 implicit-GEMM conv + fused gate epilogue.
// D[px, co] = sum_k A[px,k] * W[co,k];  k = (kh*3+kw)*16 + ci.
// CTA: 128 thr; tile M=128 px (2 rows x 64 w) x N=64 co (co-half q).
// Warps 2(m) x 2(n); warp tile 64x32 -> acc[4][4][4].
// A read directly from shifted x tile in smem (no im2col); B staged once.
// Gate epilogue needs all 4 gates per (px,chan) -> stage accums via smem.
// ---------------------------------------------------------------------------
__global__ void __launch_bounds__(128, 3)
conv_gates_mma_kernel(const float* __restrict__ x,
                      const float* __restrict__ Wt,
                      const float* __restrict__ bias)
{
    extern __shared__ char sm[];
    uint32_t* un  = (uint32_t*)sm;                    // x tile / stage union
    uint32_t* ws  = (uint32_t*)(sm + UNION_BYTES);    // weights [64][148]
    float*    bsp = (float*)(sm + UNION_BYTES + WS_BYTES);

    const int tid  = threadIdx.x;
    const int lane = tid & 31;
    const int wid  = tid >> 5;
    const int gid  = lane >> 2;     // 0..7
    const int tig  = lane & 3;      // 0..3
    const int wm   = wid & 1;       // m-half -> output row within tile
    const int wn   = wid >> 1;      // n-half
    const int n_base = wn * 32;

    const int q   = blockIdx.x & 1;    // co-half: hid chans q*16..q*16+15
    const int uid = blockIdx.x >> 1;   // 0..147

    // ---- stage weights (tf32 bit-patterns) + bias, once per CTA ----
    // local co lc = g*16 + t  ->  global co = g*32 + q*16 + t
    for (int i = tid; i < 64 * 144; i += 128) {
        int lc = i / 144, k = i - lc * 144;
        int cc = k >> 4, ci = k & 15;
        int co = ((lc >> 4) << 5) + (q << 4) + (lc & 15);
        ws[lc * WS_CO_STRIDE + k] = to_tf32(__ldg(&Wt[(co * 16 + ci) * 9 + cc]));
    }
    if (tid < 64)
        bsp[tid] = bias[((tid >> 4) << 5) + (q << 4) + (tid & 15)];

    // ---- persistent loop over (image, row-pair) work units ----
    for (int u = uid; u < 4096; u += 148) {
        const int n  = u >> 5;
        const int h0 = (u & 31) << 1;

        __syncthreads();   // prior-iter stage reads (and initial ws fill) done
        // load x tile: rows h0-1..h0+2, cols -1..64, tf32-rounded
        const float* xn = x + (size_t)n * CIN * HWELEMS;
        for (int i = tid; i < CIN * 4 * 66; i += 128) {
            int col = i % 66;
            int row = (i / 66) & 3;
            int ci  = i / 264;
            int gr = h0 - 1 + row;
            int gc = col - 1;
            float v = 0.0f;
            if ((unsigned)gr < HH && (unsigned)gc < WW)
                v = __ldg(&xn[(ci * HH + gr) * WW + gc]);
            un[ci * XS_CI_STRIDE + row * XROW_STRIDE + col] = to_tf32(v);
        }
        __syncthreads();

        // ---- GEMM mainloop: 9 taps x 2 ci-halves (K chunks of 8) ----
        float acc[4][4][4];
        #pragma unroll
        for (int mf = 0; mf < 4; mf++)
            #pragma unroll
            for (int nf = 0; nf < 4; nf++)
                #pragma unroll
                for (int e = 0; e < 4; e++) acc[mf][nf][e] = 0.0f;

        #pragma unroll
        for (int cc = 0; cc < 9; cc++) {
            const int kh = cc / 3;
            const int kw = cc - kh * 3;
            #pragma unroll
            for (int hf = 0; hf < 2; hf++) {
                const int kc  = cc * 2 + hf;
                const int cib = hf << 3;
                // A: px row = wm, w = mf*16 + gid (+8); k-col -> ci = cib + tig (+4)
                const uint32_t* ab = un + (cib + tig) * XS_CI_STRIDE
                                        + (wm + kh) * XROW_STRIDE + kw + gid;
                // B: local co = n_base + nf*8 + gid; k = kc*8 + tig (+4)
                const uint32_t* bb = ws + (n_base + gid) * WS_CO_STRIDE + (kc << 3) + tig;

                uint32_t bf[4][2];
                #pragma unroll
                for (int nf = 0; nf < 4; nf++) {
                    bf[nf][0] = bb[nf * 8 * WS_CO_STRIDE];
                    bf[nf][1] = bb[nf * 8 * WS_CO_STRIDE + 4];
                }
                #pragma unroll
                for (int mf = 0; mf < 4; mf++) {
                    uint32_t af[4];
                    af[0] = ab[mf * 16];
                    af[1] = ab[mf * 16 + 8];
                    af[2] = ab[mf * 16 + 4 * XS_CI_STRIDE];
                    af[3] = ab[mf * 16 + 8 + 4 * XS_CI_STRIDE];
                    #pragma unroll
                    for (int nf = 0; nf < 4; nf++)
                        mma_tf32(acc[mf][nf], af, bf[nf]);
                }
            }
        }

        __syncthreads();   // all warps done reading x tile
        // ---- stage accums to smem [px][co] (stride 68) ----
        float* unf = (float*)un;
        #pragma unroll
        for (int mf = 0; mf < 4; mf++) {
            const int px0 = wm * 64 + mf * 16 + gid;
            #pragma unroll
            for (int nf = 0; nf < 4; nf++) {
                const int co0 = n_base + nf * 8 + tig * 2;
                *(float2*)&unf[px0 * STAGE_STRIDE + co0] =
                    make_float2(acc[mf][nf][0], acc[mf][nf][1]);
                *(float2*)&unf[(px0 + 8) * STAGE_STRIDE + co0] =
                    make_float2(acc[mf][nf][2], acc[mf][nf][3]);
            }
        }
        __syncthreads();

        // ---- fused gate epilogue: thread = pixel, 64 co = 4 gates x 16 ch ----
        float d[64];
        #pragma unroll
        for (int j4 = 0; j4 < 16; j4++) {
            float4 v = *(float4*)&unf[tid * STAGE_STRIDE + j4 * 4];
            d[j4 * 4]     = v.x;
            d[j4 * 4 + 1] = v.y;
            d[j4 * 4 + 2] = v.z;
            d[j4 * 4 + 3] = v.w;
        }
        const int h = h0 + (tid >> 6);
        const int w = tid & 63;
        const size_t PL = (size_t)HID * HWELEMS;
        size_t base0 = (((size_t)n * 3) * HID + (q << 4)) * HWELEMS
                       + (size_t)h * WW + w;
        #pragma unroll
        for (int j = 0; j < 16; j++) {
            float iv = d[j]      + bsp[j];
            float fv = d[16 + j] + bsp[16 + j];
            float ov = d[32 + j] + bsp[32 + j];
            float cv = d[48 + j] + bsp[48 + j];
            float ei  = __expf(-iv);
            float ef  = __expf(-fv);
            float inv = __fdividef(1.f, 2.f + ei + ef);
            float fp  = (1.f + ei) * inv;                       // f'
            float ip  = (1.f + ef) * inv;                       // i'
            float g   = (cv >= 0.f) ? (cv + 0.5f)
                      : __fdividef(1.f, 1.f + __expf(-cv));
            float so  = __fdividef(1.f, 1.f + __expf(-ov));
            size_t bj = base0 + (size_t)j * HWELEMS;
            sc_scratch[bj]          = fp;
            sc_scratch[bj + PL]     = ip * g;
            sc_scratch[bj + 2 * PL] = so;
        }
    }
}

// ---------------------------------------------------------------------------
// Scan: pure streaming recurrence (proven: 44us, DRAM-bound).
// ---------------------------------------------------------------------------
__global__ void __launch_bounds__(256)
lstm_scan_kernel(const float* __restrict__ c0,
                 float* __restrict__ out,
                 float* __restrict__ clast)
{
    const int idx = blockIdx.x * blockDim.x + threadIdx.x;
    const int hw = idx & 4095;
    const int ch = (idx >> 12) & 31;
    const int b  = idx >> 17;

    float cs = c0[((size_t)b * HID + ch) * HWELEMS + hw];
    const size_t PL = (size_t)HID * HWELEMS;
    const size_t ST = 3 * PL;
    const float* sp = sc_scratch + (size_t)(b * SS) * ST + (size_t)ch * HWELEMS + hw;
    float* op = out + ((size_t)(b * SS) * HID + ch) * HWELEMS + hw;

    #pragma unroll 4
    for (int s = 0; s < SS; s++) {
        float fp = __ldg(sp);
        float ig = __ldg(sp + PL);
        float so = __ldg(sp + 2 * PL);
        cs = fmaf(fp, cs, ig);
        *op = so * cs;
        sp += ST;
        op += PL;
    }
    clast[((size_t)b * HID + ch) * HWELEMS + hw] = cs;
}

// ---------------------------------------------------------------------------
extern "C" void kernel_launch(void* const* d_in, const int* in_sizes, int n_in,
                              void* d_out, int out_size)
{
    const float* x  = (const float*)d_in[0];   // (2,64,16,64,64)
    const float* Wt = (const float*)d_in[1];   // (128,16,3,3)
    const float* b  = (const float*)d_in[2];   // (128)
    const float* c0 = (const float*)d_in[3];   // (2,1,32,64,64)

    float* out   = (float*)d_out;                              // (2,64,32,64,64)
    float* clast = out + (size_t)BB * SS * HID * HWELEMS;      // (2,1,32,64,64)

    cudaFuncSetAttribute(conv_gates_mma_kernel,
                         cudaFuncAttributeMaxDynamicSharedMemorySize, SMEM_DYN);

    conv_gates_mma_kernel<<<296, 128, SMEM_DYN>>>(x, Wt, b);

    const int total = BB * HID * HWELEMS;      // 262144
    lstm_scan_kernel<<<total / 256, 256>>>(c0, out, clast);
}

// round 8
// speedup vs baseline: 4.2485x; 2.2660x over previous
#include <cuda_runtime.h>
#include <cuda_fp16.h>
#include <cstdint>

// Problem dims (fixed)
#define BB   2
#define SS   64
#define CIN  16
#define HID  32
#define COUT 128
#define HH   64
#define WW   64
#define NN   (BB*SS)      // 128
#define HWELEMS (HH*WW)   // 4096

// scratch: [n][3][hid][h][w] : plane 0 = f', 1 = i'*g(cell), 2 = sigmoid(o)
__device__ float sc_scratch[(size_t)NN * 3 * HID * HWELEMS];

// x tile: [6 rows][66 cols][24 halves(16 ci + 8 pad)] -> uint32 words
#define XT_COL_W   12                 // words per col (24 halves)
#define XT_ROW_W   (66 * XT_COL_W)   // 792
#define XT_WORDS   (6 * XT_ROW_W)    // 4752 words = 19008 B
// weights: [64 lc][152 halves(144 k + 8 pad)] -> 76 words per lc
#define WS_LC_W    76
#define WS_WORDS   (64 * WS_LC_W)    // 4864 words = 19456 B

__device__ __forceinline__ void mma_f16(float* d, const uint32_t* a, const uint32_t* b) {
    asm volatile(
        "mma.sync.aligned.m16n8k16.row.col.f32.f16.f16.f32 "
        "{%0,%1,%2,%3}, {%4,%5,%6,%7}, {%8,%9}, {%0,%1,%2,%3};"
        : "+f"(d[0]), "+f"(d[1]), "+f"(d[2]), "+f"(d[3])
        : "r"(a[0]), "r"(a[1]), "r"(a[2]), "r"(a[3]), "r"(b[0]), "r"(b[1]));
}
__device__ __forceinline__ uint32_t pack_h2(float lo, float hi) {
    __half2 h = __floats2half2_rn(lo, hi);
    return *reinterpret_cast<uint32_t*>(&h);
}

// ---------------------------------------------------------------------------
// fp16 implicit-GEMM conv + in-register gate epilogue.
// D[px, co] = sum_k A[px,k] W[co,k];  k-chunk = one 3x3 tap (16 ci, fp16 k16).
// CTA: 256 thr, tile M=256 px (4 rows x 64 w) x N=64 co (co-half q).
// Warps 4(m) x 2(n); warp tile 64 px x 32 co, where the 32 co are
// 4 gates x 8 channels -> each thread's accumulators hold all 4 gates for
// its (px, chan) pairs -> gate nonlinearity fused in registers, no smem stage.
// ---------------------------------------------------------------------------
__global__ void __launch_bounds__(256, 2)
conv_gates_mma_kernel(const float* __restrict__ x,
                      const float* __restrict__ Wt,
                      const float* __restrict__ bias)
{
    __shared__ uint32_t xt[XT_WORDS];
    __shared__ uint32_t ws[WS_WORDS];
    __shared__ float    bsp[64];

    const int tid  = threadIdx.x;
    const int lane = tid & 31;
    const int wid  = tid >> 5;
    const int gid  = lane >> 2;     // 0..7
    const int tig  = lane & 3;      // 0..3
    const int wm   = wid & 3;       // spatial row within 4-row tile
    const int wn   = wid >> 2;      // channel group (8 chans)

    const int q   = blockIdx.x & 1;    // co-half: hid chans q*16..q*16+15
    const int uid = blockIdx.x >> 1;   // 0..147

    // ---- stage weights as fp16 pairs: ws[lc][k], lc = g*16 + chan_local ----
    for (int i = tid; i < 64 * 72; i += 256) {
        int lc = i / 72, kw2 = i - lc * 72;      // word in k (2 halves)
        int k0 = kw2 * 2;
        int cc = k0 >> 4, ci = k0 & 15;          // ci, ci+1 share tap cc
        int co = ((lc >> 4) << 5) + (q << 4) + (lc & 15);
        float v0 = __ldg(&Wt[(co * 16 + ci)     * 9 + cc]);
        float v1 = __ldg(&Wt[(co * 16 + ci + 1) * 9 + cc]);
        ws[lc * WS_LC_W + kw2] = pack_h2(v0, v1);
    }
    if (tid < 64)
        bsp[tid] = bias[((tid >> 4) << 5) + (q << 4) + (tid & 15)];

    const int cl0 = wn * 8 + tig * 2;   // chan_local for even accum cols

    // ---- persistent loop over (image, 4-row tile) units ----
    for (int u = uid; u < 2048; u += 148) {
        const int n  = u >> 4;
        const int h0 = (u & 15) << 2;

        __syncthreads();   // all warps done reading xt from prior iter
        // load x tile rows h0-1..h0+4, cols -1..64, transposed to [row][col][ci]
        const float* xn = x + (size_t)n * CIN * HWELEMS;
        for (int pidx = tid; pidx < 6 * 66; pidx += 256) {
            int row = pidx / 66;
            int col = pidx - row * 66;
            int gr = h0 - 1 + row;
            int gc = col - 1;
            uint32_t* dst = &xt[row * XT_ROW_W + col * XT_COL_W];
            if ((unsigned)gr < HH && (unsigned)gc < WW) {
                const float* src = xn + gr * WW + gc;
                #pragma unroll
                for (int j = 0; j < 8; j++)
                    dst[j] = pack_h2(__ldg(src + (2 * j) * HWELEMS),
                                     __ldg(src + (2 * j + 1) * HWELEMS));
            } else {
                #pragma unroll
                for (int j = 0; j < 8; j++) dst[j] = 0u;
            }
        }
        __syncthreads();

        // ---- GEMM mainloop: 9 taps, k16 per tap ----
        float acc[4][4][4];   // [mf][gate][frag]
        #pragma unroll
        for (int mf = 0; mf < 4; mf++)
            #pragma unroll
            for (int g = 0; g < 4; g++)
                #pragma unroll
                for (int e = 0; e < 4; e++) acc[mf][g][e] = 0.0f;

        #pragma unroll
        for (int cc = 0; cc < 9; cc++) {
            const int kh = cc / 3;
            const int kw = cc - kh * 3;
            // B frags: b[g][2], lane holds k = tig*2(+1), (+8); n(chan) = gid
            uint32_t bf[4][2];
            #pragma unroll
            for (int g = 0; g < 4; g++) {
                const uint32_t* bb = &ws[((g << 4) + (wn << 3) + gid) * WS_LC_W + (cc << 3) + tig];
                bf[g][0] = bb[0];
                bf[g][1] = bb[4];
            }
            const uint32_t* ab0 = &xt[(wm + kh) * XT_ROW_W + (gid + kw) * XT_COL_W + tig];
            #pragma unroll
            for (int mf = 0; mf < 4; mf++) {
                const uint32_t* ab = ab0 + mf * 16 * XT_COL_W;
                uint32_t af[4];
                af[0] = ab[0];                       // row gid,   k 0-7 part
                af[1] = ab[8 * XT_COL_W];            // row gid+8
                af[2] = ab[4];                       // row gid,   k 8-15 part
                af[3] = ab[8 * XT_COL_W + 4];        // row gid+8
                #pragma unroll
                for (int g = 0; g < 4; g++)
                    mma_f16(acc[mf][g], af, bf[g]);
            }
        }

        // ---- in-register gate epilogue -> scratch ----
        const int h = h0 + wm;
        const size_t PL = (size_t)HID * HWELEMS;
        const float bI0 = bsp[cl0],      bI1 = bsp[cl0 + 1];
        const float bF0 = bsp[16 + cl0], bF1 = bsp[16 + cl0 + 1];
        const float bO0 = bsp[32 + cl0], bO1 = bsp[32 + cl0 + 1];
        const float bC0 = bsp[48 + cl0], bC1 = bsp[48 + cl0 + 1];
        #pragma unroll
        for (int mf = 0; mf < 4; mf++) {
            #pragma unroll
            for (int eh = 0; eh < 2; eh++) {        // px halves (row gid / gid+8)
                const int w = mf * 16 + gid + eh * 8;
                #pragma unroll
                for (int ec = 0; ec < 2; ec++) {    // chan pair
                    const int e = eh * 2 + ec;
                    float iv = acc[mf][0][e] + (ec ? bI1 : bI0);
                    float fv = acc[mf][1][e] + (ec ? bF1 : bF0);
                    float ov = acc[mf][2][e] + (ec ? bO1 : bO0);
                    float cv = acc[mf][3][e] + (ec ? bC1 : bC0);
                    float ei  = __expf(-iv);
                    float ef  = __expf(-fv);
                    float inv = __fdividef(1.f, 2.f + ei + ef);
                    float fp  = (1.f + ei) * inv;                   // f'
                    float ip  = (1.f + ef) * inv;                   // i'
                    float g   = (cv >= 0.f) ? (cv + 0.5f)
                              : __fdividef(1.f, 1.f + __expf(-cv));
                    float so  = __fdividef(1.f, 1.f + __expf(-ov));
                    const int chan = (q << 4) + cl0 + ec;
                    size_t base = (((size_t)n * 3) * HID + chan) * HWELEMS
                                  + (size_t)h * WW + w;
                    sc_scratch[base]          = fp;
                    sc_scratch[base + PL]     = ip * g;
                    sc_scratch[base + 2 * PL] = so;
                }
            }
        }
    }
}

// ---------------------------------------------------------------------------
// Scan: pure streaming recurrence (proven: ~45us, DRAM-bound).
// ---------------------------------------------------------------------------
__global__ void __launch_bounds__(256)
lstm_scan_kernel(const float* __restrict__ c0,
                 float* __restrict__ out,
                 float* __restrict__ clast)
{
    const int idx = blockIdx.x * blockDim.x + threadIdx.x;
    const int hw = idx & 4095;
    const int ch = (idx >> 12) & 31;
    const int b  = idx >> 17;

    float cs = c0[((size_t)b * HID + ch) * HWELEMS + hw];
    const size_t PL = (size_t)HID * HWELEMS;
    const size_t ST = 3 * PL;
    const float* sp = sc_scratch + (size_t)(b * SS) * ST + (size_t)ch * HWELEMS + hw;
    float* op = out + ((size_t)(b * SS) * HID + ch) * HWELEMS + hw;

    #pragma unroll 4
    for (int s = 0; s < SS; s++) {
        float fp = __ldg(sp);
        float ig = __ldg(sp + PL);
        float so = __ldg(sp + 2 * PL);
        cs = fmaf(fp, cs, ig);
        *op = so * cs;
        sp += ST;
        op += PL;
    }
    clast[((size_t)b * HID + ch) * HWELEMS + hw] = cs;
}

// ---------------------------------------------------------------------------
extern "C" void kernel_launch(void* const* d_in, const int* in_sizes, int n_in,
                              void* d_out, int out_size)
{
    const float* x  = (const float*)d_in[0];   // (2,64,16,64,64)
    const float* Wt = (const float*)d_in[1];   // (128,16,3,3)
    const float* b  = (const float*)d_in[2];   // (128)
    const float* c0 = (const float*)d_in[3];   // (2,1,32,64,64)

    float* out   = (float*)d_out;                              // (2,64,32,64,64)
    float* clast = out + (size_t)BB * SS * HID * HWELEMS;      // (2,1,32,64,64)

    conv_gates_mma_kernel<<<296, 256>>>(x, Wt, b);

    const int total = BB * HID * HWELEMS;      // 262144
    lstm_scan_kernel<<<total / 256, 256>>>(c0, out, clast);
}

// round 9
// speedup vs baseline: 4.4250x; 1.0415x over previous
#include <cuda_runtime.h>
#include <cuda_fp16.h>
#include <cstdint>

// Problem dims (fixed)
#define BB   2
#define SS   64
#define CIN  16
#define HID  32
#define COUT 128
#define HH   64
#define WW   64
#define NN   (BB*SS)      // 128
#define HWELEMS (HH*WW)   // 4096

// scratch: [n][3][hid][h][w] : plane 0 = f', 1 = i'*g(cell), 2 = sigmoid(o)
__device__ float sc_scratch[(size_t)NN * 3 * HID * HWELEMS];

// x tile: [6 rows][66 cols][24 halves(16 ci + 8 pad)] -> uint32 words
#define XT_COL_W   12                 // words per col (24 halves)
#define XT_ROW_W   (66 * XT_COL_W)    // 792
#define XT_WORDS   (6 * XT_ROW_W)     // 4752 words = 19008 B
// weights: [64 lc][152 halves(144 k + 8 pad)] -> 76 words per lc
#define WS_LC_W    76
#define WS_WORDS   (64 * WS_LC_W)     // 4864 words = 19456 B
// dynamic smem: xt[2] | ws | bias
#define SMEM_DYN   ((2 * XT_WORDS + WS_WORDS) * 4 + 256)   // 57728

__device__ __forceinline__ void mma_f16(float* d, const uint32_t* a, const uint32_t* b) {
    asm volatile(
        "mma.sync.aligned.m16n8k16.row.col.f32.f16.f16.f32 "
        "{%0,%1,%2,%3}, {%4,%5,%6,%7}, {%8,%9}, {%0,%1,%2,%3};"
        : "+f"(d[0]), "+f"(d[1]), "+f"(d[2]), "+f"(d[3])
        : "r"(a[0]), "r"(a[1]), "r"(a[2]), "r"(a[3]), "r"(b[0]), "r"(b[1]));
}
__device__ __forceinline__ uint32_t pack_h2(float lo, float hi) {
    __half2 h = __floats2half2_rn(lo, hi);
    return *reinterpret_cast<uint32_t*>(&h);
}

// Load one x-tile position (row,col) as 8 packed fp16x2 words (16 ci).
__device__ __forceinline__ void load_pos(const float* __restrict__ xn, int h0,
                                         int pidx, uint32_t* pr) {
    const int row = pidx / 66;
    const int col = pidx - row * 66;
    const int gr = h0 - 1 + row;
    const int gc = col - 1;
    if ((unsigned)gr < HH && (unsigned)gc < WW) {
        const float* src = xn + gr * WW + gc;
        #pragma unroll
        for (int j = 0; j < 8; j++)
            pr[j] = pack_h2(__ldg(src + (2 * j) * HWELEMS),
                            __ldg(src + (2 * j + 1) * HWELEMS));
    } else {
        #pragma unroll
        for (int j = 0; j < 8; j++) pr[j] = 0u;
    }
}
__device__ __forceinline__ void sts_pos(uint32_t* xtb, int pidx, const uint32_t* pr) {
    const int row = pidx / 66;
    const int col = pidx - row * 66;
    uint32_t* dst = xtb + row * XT_ROW_W + col * XT_COL_W;
    *(uint4*)(dst)     = make_uint4(pr[0], pr[1], pr[2], pr[3]);
    *(uint4*)(dst + 4) = make_uint4(pr[4], pr[5], pr[6], pr[7]);
}

// ---------------------------------------------------------------------------
// fp16 implicit-GEMM conv + in-register gate epilogue, software-pipelined:
// next x tile is LDG'd+packed into registers before the MMA loop (latency
// hidden under HMMA), STS'd to the back buffer after, 1 sync per iteration.
// CTA: 256 thr, tile M=256 px (4 rows x 64 w) x N=64 co (co-half q).
// Warps 4(m) x 2(n); warp N-tile = 4 gates x 8 chans -> gates fused in regs.
// ---------------------------------------------------------------------------
__global__ void __launch_bounds__(256, 2)
conv_gates_mma_kernel(const float* __restrict__ x,
                      const float* __restrict__ Wt,
                      const float* __restrict__ bias)
{
    extern __shared__ uint32_t smw[];
    uint32_t* xt0 = smw;                         // tile buffer 0
    uint32_t* xt1 = smw + XT_WORDS;              // tile buffer 1
    uint32_t* ws  = smw + 2 * XT_WORDS;          // weights
    float*    bsp = (float*)(smw + 2 * XT_WORDS + WS_WORDS);

    const int tid  = threadIdx.x;
    const int lane = tid & 31;
    const int wid  = tid >> 5;
    const int gid  = lane >> 2;     // 0..7
    const int tig  = lane & 3;      // 0..3
    const int wm   = wid & 3;       // spatial row within 4-row tile
    const int wn   = wid >> 2;      // channel group (8 chans)

    const int q   = blockIdx.x & 1;    // co-half: hid chans q*16..q*16+15
    const int uid = blockIdx.x >> 1;   // 0..147

    // ---- stage weights as fp16 pairs: ws[lc][k], lc = g*16 + chan_local ----
    for (int i = tid; i < 64 * 72; i += 256) {
        int lc = i / 72, kw2 = i - lc * 72;
        int k0 = kw2 * 2;
        int cc = k0 >> 4, ci = k0 & 15;
        int co = ((lc >> 4) << 5) + (q << 4) + (lc & 15);
        float v0 = __ldg(&Wt[(co * 16 + ci)     * 9 + cc]);
        float v1 = __ldg(&Wt[(co * 16 + ci + 1) * 9 + cc]);
        ws[lc * WS_LC_W + kw2] = pack_h2(v0, v1);
    }
    if (tid < 64)
        bsp[tid] = bias[((tid >> 4) << 5) + (q << 4) + (tid & 15)];

    const int cl0 = wn * 8 + tig * 2;   // chan_local for even accum cols

    // ---- prologue: load first tile into xt0 ----
    {
        const float* xn = x + (size_t)(uid >> 4) * CIN * HWELEMS;
        const int h0 = (uid & 15) << 2;
        uint32_t pr[8];
        load_pos(xn, h0, tid, pr);
        sts_pos(xt0, tid, pr);
        if (tid + 256 < 396) {
            load_pos(xn, h0, tid + 256, pr);
            sts_pos(xt0, tid + 256, pr);
        }
    }
    __syncthreads();

    int buf = 0;
    for (int u = uid; u < 2048; u += 148) {
        const int n  = u >> 4;
        const int h0 = (u & 15) << 2;
        const int un = u + 148;
        const bool nx = (un < 2048);

        // ---- issue next-tile loads into registers (hidden under MMA) ----
        uint32_t pr0[8], pr1[8];
        if (nx) {
            const float* xn2 = x + (size_t)(un >> 4) * CIN * HWELEMS;
            const int h02 = (un & 15) << 2;
            load_pos(xn2, h02, tid, pr0);
            if (tid + 256 < 396) load_pos(xn2, h02, tid + 256, pr1);
        }

        const uint32_t* xb = buf ? xt1 : xt0;
        uint32_t* xnb      = buf ? xt0 : xt1;

        // ---- GEMM mainloop: 9 taps, k16 per tap ----
        float acc[4][4][4];   // [mf][gate][frag]
        #pragma unroll
        for (int mf = 0; mf < 4; mf++)
            #pragma unroll
            for (int g = 0; g < 4; g++)
                #pragma unroll
                for (int e = 0; e < 4; e++) acc[mf][g][e] = 0.0f;

        #pragma unroll
        for (int cc = 0; cc < 9; cc++) {
            const int kh = cc / 3;
            const int kw = cc - kh * 3;
            uint32_t bf[4][2];
            #pragma unroll
            for (int g = 0; g < 4; g++) {
                const uint32_t* bb = &ws[((g << 4) + (wn << 3) + gid) * WS_LC_W + (cc << 3) + tig];
                bf[g][0] = bb[0];
                bf[g][1] = bb[4];
            }
            const uint32_t* ab0 = &xb[(wm + kh) * XT_ROW_W + (gid + kw) * XT_COL_W + tig];
            #pragma unroll
            for (int mf = 0; mf < 4; mf++) {
                const uint32_t* ab = ab0 + mf * 16 * XT_COL_W;
                uint32_t af[4];
                af[0] = ab[0];
                af[1] = ab[8 * XT_COL_W];
                af[2] = ab[4];
                af[3] = ab[8 * XT_COL_W + 4];
                #pragma unroll
                for (int g = 0; g < 4; g++)
                    mma_f16(acc[mf][g], af, bf[g]);
            }
        }

        // ---- store next tile to back buffer (frees pipeline regs) ----
        if (nx) {
            sts_pos(xnb, tid, pr0);
            if (tid + 256 < 396) sts_pos(xnb, tid + 256, pr1);
        }

        // ---- in-register gate epilogue -> scratch ----
        const int h = h0 + wm;
        const size_t PL = (size_t)HID * HWELEMS;
        const float bI0 = bsp[cl0],      bI1 = bsp[cl0 + 1];
        const float bF0 = bsp[16 + cl0], bF1 = bsp[16 + cl0 + 1];
        const float bO0 = bsp[32 + cl0], bO1 = bsp[32 + cl0 + 1];
        const float bC0 = bsp[48 + cl0], bC1 = bsp[48 + cl0 + 1];
        #pragma unroll
        for (int mf = 0; mf < 4; mf++) {
            #pragma unroll
            for (int eh = 0; eh < 2; eh++) {
                const int w = mf * 16 + gid + eh * 8;
                #pragma unroll
                for (int ec = 0; ec < 2; ec++) {
                    const int e = eh * 2 + ec;
                    float iv = acc[mf][0][e] + (ec ? bI1 : bI0);
                    float fv = acc[mf][1][e] + (ec ? bF1 : bF0);
                    float ov = acc[mf][2][e] + (ec ? bO1 : bO0);
                    float cv = acc[mf][3][e] + (ec ? bC1 : bC0);
                    float ei  = __expf(-iv);
                    float ef  = __expf(-fv);
                    float inv = __fdividef(1.f, 2.f + ei + ef);
                    float fp  = (1.f + ei) * inv;                   // f'
                    float ip  = (1.f + ef) * inv;                   // i'
                    float g   = (cv >= 0.f) ? (cv + 0.5f)
                              : __fdividef(1.f, 1.f + __expf(-cv));
                    float so  = __fdividef(1.f, 1.f + __expf(-ov));
                    const int chan = (q << 4) + cl0 + ec;
                    size_t base = (((size_t)n * 3) * HID + chan) * HWELEMS
                                  + (size_t)h * WW + w;
                    sc_scratch[base]          = fp;
                    sc_scratch[base + PL]     = ip * g;
                    sc_scratch[base + 2 * PL] = so;
                }
            }
        }

        __syncthreads();   // STS to back buffer visible before next MMA
        buf ^= 1;
    }
}

// ---------------------------------------------------------------------------
// Scan: streaming recurrence, 4 sequences per thread (float4) for MLP.
// ---------------------------------------------------------------------------
__global__ void __launch_bounds__(256)
lstm_scan_kernel(const float* __restrict__ c0,
                 float* __restrict__ out,
                 float* __restrict__ clast)
{
    const int t  = blockIdx.x * blockDim.x + threadIdx.x;   // 0..65535
    const int hw = (t & 1023) << 2;
    const int ch = (t >> 10) & 31;
    const int b  = t >> 15;

    float4 cs = *(const float4*)&c0[((size_t)b * HID + ch) * HWELEMS + hw];
    const size_t PL = (size_t)HID * HWELEMS;
    const size_t ST = 3 * PL;
    const float* sp = sc_scratch + (size_t)(b * SS) * ST + (size_t)ch * HWELEMS + hw;
    float* op = out + ((size_t)(b * SS) * HID + ch) * HWELEMS + hw;

    #pragma unroll 4
    for (int s = 0; s < SS; s++) {
        float4 fp = *(const float4*)sp;
        float4 ig = *(const float4*)(sp + PL);
        float4 so = *(const float4*)(sp + 2 * PL);
        cs.x = fmaf(fp.x, cs.x, ig.x);
        cs.y = fmaf(fp.y, cs.y, ig.y);
        cs.z = fmaf(fp.z, cs.z, ig.z);
        cs.w = fmaf(fp.w, cs.w, ig.w);
        *(float4*)op = make_float4(so.x * cs.x, so.y * cs.y,
                                   so.z * cs.z, so.w * cs.w);
        sp += ST;
        op += PL;
    }
    *(float4*)&clast[((size_t)b * HID + ch) * HWELEMS + hw] = cs;
}

// ---------------------------------------------------------------------------
extern "C" void kernel_launch(void* const* d_in, const int* in_sizes, int n_in,
                              void* d_out, int out_size)
{
    const float* x  = (const float*)d_in[0];   // (2,64,16,64,64)
    const float* Wt = (const float*)d_in[1];   // (128,16,3,3)
    const float* b  = (const float*)d_in[2];   // (128)
    const float* c0 = (const float*)d_in[3];   // (2,1,32,64,64)

    float* out   = (float*)d_out;                              // (2,64,32,64,64)
    float* clast = out + (size_t)BB * SS * HID * HWELEMS;      // (2,1,32,64,64)

    cudaFuncSetAttribute(conv_gates_mma_kernel,
                         cudaFuncAttributeMaxDynamicSharedMemorySize, SMEM_DYN);

    conv_gates_mma_kernel<<<296, 256, SMEM_DYN>>>(x, Wt, b);

    const int total4 = BB * HID * HWELEMS / 4;   // 65536
    lstm_scan_kernel<<<total4 / 256, 256>>>(c0, out, clast);
}

// round 10
// speedup vs baseline: 5.4738x; 1.2370x over previous
#include <cuda_runtime.h>
#include <cuda_fp16.h>
#include <cstdint>

// Problem dims (fixed)
#define BB   2
#define SS   64
#define CIN  16
#define HID  32
#define COUT 128
#define HH   64
#define WW   64
#define NN   (BB*SS)      // 128
#define HWELEMS (HH*WW)   // 4096

// scratch plane A: [n][hid][hw] packed half2(f', i'*g)   (67 MB)
// scratch plane B: [n][hid][hw] half sigmoid(o)          (33.5 MB)
__device__ uint32_t scA[(size_t)NN * HID * HWELEMS];
__device__ __half   scB[(size_t)NN * HID * HWELEMS];

// x tile: [6 rows][66 cols][24 halves(16 ci + 8 pad)] -> uint32 words
#define XT_COL_W   12                 // words per col (24 halves)
#define XT_ROW_W   (66 * XT_COL_W)    // 792
#define XT_WORDS   (6 * XT_ROW_W)     // 4752 words = 19008 B
// weights: [64 lc][152 halves(144 k + 8 pad)] -> 76 words per lc
#define WS_LC_W    76
#define WS_WORDS   (64 * WS_LC_W)     // 4864 words = 19456 B
// dynamic smem: xt[2] | ws | bias
#define SMEM_DYN   ((2 * XT_WORDS + WS_WORDS) * 4 + 256)   // 57728

__device__ __forceinline__ void mma_f16(float* d, const uint32_t* a, const uint32_t* b) {
    asm volatile(
        "mma.sync.aligned.m16n8k16.row.col.f32.f16.f16.f32 "
        "{%0,%1,%2,%3}, {%4,%5,%6,%7}, {%8,%9}, {%0,%1,%2,%3};"
        : "+f"(d[0]), "+f"(d[1]), "+f"(d[2]), "+f"(d[3])
        : "r"(a[0]), "r"(a[1]), "r"(a[2]), "r"(a[3]), "r"(b[0]), "r"(b[1]));
}
__device__ __forceinline__ uint32_t pack_h2(float lo, float hi) {
    __half2 h = __floats2half2_rn(lo, hi);
    return *reinterpret_cast<uint32_t*>(&h);
}

// Load one x-tile position (row,col) as 8 packed fp16x2 words (16 ci).
__device__ __forceinline__ void load_pos(const float* __restrict__ xn, int h0,
                                         int pidx, uint32_t* pr) {
    const int row = pidx / 66;
    const int col = pidx - row * 66;
    const int gr = h0 - 1 + row;
    const int gc = col - 1;
    if ((unsigned)gr < HH && (unsigned)gc < WW) {
        const float* src = xn + gr * WW + gc;
        #pragma unroll
        for (int j = 0; j < 8; j++)
            pr[j] = pack_h2(__ldg(src + (2 * j) * HWELEMS),
                            __ldg(src + (2 * j + 1) * HWELEMS));
    } else {
        #pragma unroll
        for (int j = 0; j < 8; j++) pr[j] = 0u;
    }
}
__device__ __forceinline__ void sts_pos(uint32_t* xtb, int pidx, const uint32_t* pr) {
    const int row = pidx / 66;
    const int col = pidx - row * 66;
    uint32_t* dst = xtb + row * XT_ROW_W + col * XT_COL_W;
    *(uint4*)(dst)     = make_uint4(pr[0], pr[1], pr[2], pr[3]);
    *(uint4*)(dst + 4) = make_uint4(pr[4], pr[5], pr[6], pr[7]);
}

// ---------------------------------------------------------------------------
// fp16 implicit-GEMM conv + in-register gate epilogue, software-pipelined.
// CTA: 256 thr, tile M=256 px (4 rows x 64 w) x N=64 co (co-half q).
// Warps 4(m) x 2(n); warp N-tile = 4 gates x 8 chans -> gates fused in regs.
// Epilogue writes fp16 gate planes (halves scratch DRAM traffic).
// ---------------------------------------------------------------------------
__global__ void __launch_bounds__(256, 2)
conv_gates_mma_kernel(const float* __restrict__ x,
                      const float* __restrict__ Wt,
                      const float* __restrict__ bias)
{
    extern __shared__ uint32_t smw[];
    uint32_t* xt0 = smw;
    uint32_t* xt1 = smw + XT_WORDS;
    uint32_t* ws  = smw + 2 * XT_WORDS;
    float*    bsp = (float*)(smw + 2 * XT_WORDS + WS_WORDS);

    const int tid  = threadIdx.x;
    const int lane = tid & 31;
    const int wid  = tid >> 5;
    const int gid  = lane >> 2;     // 0..7
    const int tig  = lane & 3;      // 0..3
    const int wm   = wid & 3;       // spatial row within 4-row tile
    const int wn   = wid >> 2;      // channel group (8 chans)

    const int q   = blockIdx.x & 1;    // co-half: hid chans q*16..q*16+15
    const int uid = blockIdx.x >> 1;   // 0..147

    // ---- stage weights as fp16 pairs: ws[lc][k], lc = g*16 + chan_local ----
    for (int i = tid; i < 64 * 72; i += 256) {
        int lc = i / 72, kw2 = i - lc * 72;
        int k0 = kw2 * 2;
        int cc = k0 >> 4, ci = k0 & 15;
        int co = ((lc >> 4) << 5) + (q << 4) + (lc & 15);
        float v0 = __ldg(&Wt[(co * 16 + ci)     * 9 + cc]);
        float v1 = __ldg(&Wt[(co * 16 + ci + 1) * 9 + cc]);
        ws[lc * WS_LC_W + kw2] = pack_h2(v0, v1);
    }
    if (tid < 64)
        bsp[tid] = bias[((tid >> 4) << 5) + (q << 4) + (tid & 15)];

    const int cl0 = wn * 8 + tig * 2;   // chan_local for even accum cols

    // ---- prologue: load first tile into xt0 ----
    {
        const float* xn = x + (size_t)(uid >> 4) * CIN * HWELEMS;
        const int h0 = (uid & 15) << 2;
        uint32_t pr[8];
        load_pos(xn, h0, tid, pr);
        sts_pos(xt0, tid, pr);
        if (tid + 256 < 396) {
            load_pos(xn, h0, tid + 256, pr);
            sts_pos(xt0, tid + 256, pr);
        }
    }
    __syncthreads();

    int buf = 0;
    for (int u = uid; u < 2048; u += 148) {
        const int n  = u >> 4;
        const int h0 = (u & 15) << 2;
        const int un = u + 148;
        const bool nx = (un < 2048);

        // ---- issue next-tile loads into registers (hidden under MMA) ----
        uint32_t pr0[8], pr1[8];
        if (nx) {
            const float* xn2 = x + (size_t)(un >> 4) * CIN * HWELEMS;
            const int h02 = (un & 15) << 2;
            load_pos(xn2, h02, tid, pr0);
            if (tid + 256 < 396) load_pos(xn2, h02, tid + 256, pr1);
        }

        const uint32_t* xb = buf ? xt1 : xt0;
        uint32_t* xnb      = buf ? xt0 : xt1;

        // ---- GEMM mainloop: 9 taps, k16 per tap ----
        float acc[4][4][4];   // [mf][gate][frag]
        #pragma unroll
        for (int mf = 0; mf < 4; mf++)
            #pragma unroll
            for (int g = 0; g < 4; g++)
                #pragma unroll
                for (int e = 0; e < 4; e++) acc[mf][g][e] = 0.0f;

        #pragma unroll
        for (int cc = 0; cc < 9; cc++) {
            const int kh = cc / 3;
            const int kw = cc - kh * 3;
            uint32_t bf[4][2];
            #pragma unroll
            for (int g = 0; g < 4; g++) {
                const uint32_t* bb = &ws[((g << 4) + (wn << 3) + gid) * WS_LC_W + (cc << 3) + tig];
                bf[g][0] = bb[0];
                bf[g][1] = bb[4];
            }
            const uint32_t* ab0 = &xb[(wm + kh) * XT_ROW_W + (gid + kw) * XT_COL_W + tig];
            #pragma unroll
            for (int mf = 0; mf < 4; mf++) {
                const uint32_t* ab = ab0 + mf * 16 * XT_COL_W;
                uint32_t af[4];
                af[0] = ab[0];
                af[1] = ab[8 * XT_COL_W];
                af[2] = ab[4];
                af[3] = ab[8 * XT_COL_W + 4];
                #pragma unroll
                for (int g = 0; g < 4; g++)
                    mma_f16(acc[mf][g], af, bf[g]);
            }
        }

        // ---- store next tile to back buffer (frees pipeline regs) ----
        if (nx) {
            sts_pos(xnb, tid, pr0);
            if (tid + 256 < 396) sts_pos(xnb, tid + 256, pr1);
        }

        // ---- in-register gate epilogue -> fp16 scratch planes ----
        const int h = h0 + wm;
        const float bI0 = bsp[cl0],      bI1 = bsp[cl0 + 1];
        const float bF0 = bsp[16 + cl0], bF1 = bsp[16 + cl0 + 1];
        const float bO0 = bsp[32 + cl0], bO1 = bsp[32 + cl0 + 1];
        const float bC0 = bsp[48 + cl0], bC1 = bsp[48 + cl0 + 1];
        #pragma unroll
        for (int mf = 0; mf < 4; mf++) {
            #pragma unroll
            for (int eh = 0; eh < 2; eh++) {
                const int w = mf * 16 + gid + eh * 8;
                #pragma unroll
                for (int ec = 0; ec < 2; ec++) {
                    const int e = eh * 2 + ec;
                    float iv = acc[mf][0][e] + (ec ? bI1 : bI0);
                    float fv = acc[mf][1][e] + (ec ? bF1 : bF0);
                    float ov = acc[mf][2][e] + (ec ? bO1 : bO0);
                    float cv = acc[mf][3][e] + (ec ? bC1 : bC0);
                    float ei  = __expf(-iv);
                    float ef  = __expf(-fv);
                    float inv = __fdividef(1.f, 2.f + ei + ef);
                    float fp  = (1.f + ei) * inv;                   // f'
                    float ip  = (1.f + ef) * inv;                   // i'
                    float g   = (cv >= 0.f) ? (cv + 0.5f)
                              : __fdividef(1.f, 1.f + __expf(-cv));
                    float so  = __fdividef(1.f, 1.f + __expf(-ov));
                    const int chan = (q << 4) + cl0 + ec;
                    size_t idx = ((size_t)n * HID + chan) * HWELEMS
                                 + (size_t)h * WW + w;
                    scA[idx] = pack_h2(fp, ip * g);
                    scB[idx] = __float2half_rn(so);
                }
            }
        }

        __syncthreads();   // STS to back buffer visible before next MMA
        buf ^= 1;
    }
}

// ---------------------------------------------------------------------------
// Scan: streaming recurrence on fp16 gate planes, 2 sequences per thread.
//   c = f'*c + (i'g) ; out = sig(o)*c
// ---------------------------------------------------------------------------
__global__ void __launch_bounds__(256)
lstm_scan_kernel(const float* __restrict__ c0,
                 float* __restrict__ out,
                 float* __restrict__ clast)
{
    const int t  = blockIdx.x * blockDim.x + threadIdx.x;   // 0..131071
    const int hw = (t & 2047) << 1;
    const int ch = (t >> 11) & 31;
    const int b  = t >> 16;

    float2 cs = *(const float2*)&c0[((size_t)b * HID + ch) * HWELEMS + hw];
    const size_t ST = (size_t)HID * HWELEMS;     // per-timestep stride
    size_t idx = ((size_t)(b * SS) * HID + ch) * HWELEMS + hw;
    const uint32_t* pA = scA + idx;
    const __half*   pB = scB + idx;
    float* op = out + idx;

    #pragma unroll 4
    for (int s = 0; s < SS; s++) {
        uint2 a = *(const uint2*)pA;
        __half2 sb = *(const __half2*)pB;
        float2 v0 = __half22float2(*reinterpret_cast<__half2*>(&a.x)); // (f', ig)
        float2 v1 = __half22float2(*reinterpret_cast<__half2*>(&a.y));
        float2 so = __half22float2(sb);
        cs.x = fmaf(v0.x, cs.x, v0.y);
        cs.y = fmaf(v1.x, cs.y, v1.y);
        *(float2*)op = make_float2(so.x * cs.x, so.y * cs.y);
        pA += ST;
        pB += ST;
        op += ST;
    }
    *(float2*)&clast[((size_t)b * HID + ch) * HWELEMS + hw] = cs;
}

// ---------------------------------------------------------------------------
extern "C" void kernel_launch(void* const* d_in, const int* in_sizes, int n_in,
                              void* d_out, int out_size)
{
    const float* x  = (const float*)d_in[0];   // (2,64,16,64,64)
    const float* Wt = (const float*)d_in[1];   // (128,16,3,3)
    const float* b  = (const float*)d_in[2];   // (128)
    const float* c0 = (const float*)d_in[3];   // (2,1,32,64,64)

    float* out   = (float*)d_out;                              // (2,64,32,64,64)
    float* clast = out + (size_t)BB * SS * HID * HWELEMS;      // (2,1,32,64,64)

    cudaFuncSetAttribute(conv_gates_mma_kernel,
                         cudaFuncAttributeMaxDynamicSharedMemorySize, SMEM_DYN);

    conv_gates_mma_kernel<<<296, 256, SMEM_DYN>>>(x, Wt, b);

    const int total2 = BB * HID * HWELEMS / 2;   // 131072
    lstm_scan_kernel<<<total2 / 256, 256>>>(c0, out, clast);
}

// round 11
// speedup vs baseline: 5.7622x; 1.0527x over previous
#include <cuda_runtime.h>
#include <cuda_fp16.h>
#include <cstdint>

// Problem dims (fixed)
#define BB   2
#define SS   64
#define CIN  16
#define HID  32
#define COUT 128
#define HH   64
#define WW   64
#define NN   (BB*SS)      // 128
#define HWELEMS (HH*WW)   // 4096

// scratch plane A: [n][hid][hw] packed half2(f', i'*g)   (67 MB)
// scratch plane B: [n][hid][hw] half sigmoid(o)          (33.5 MB)
__device__ uint32_t scA[(size_t)NN * HID * HWELEMS];
__device__ __half   scB[(size_t)NN * HID * HWELEMS];

// x tile: [6 rows][66 cols][24 halves(16 ci + 8 pad)] -> uint32 words
#define XT_COL_W   12                 // words per col (24 halves)
#define XT_ROW_W   (66 * XT_COL_W)    // 792
#define XT_WORDS   (6 * XT_ROW_W)     // 4752 words = 19008 B
// weights: [64 lc][152 halves(144 k + 8 pad)] -> 76 words per lc
#define WS_LC_W    76
#define WS_WORDS   (64 * WS_LC_W)     // 4864 words = 19456 B
// dynamic smem: xt[2] | ws | bias
#define SMEM_DYN   ((2 * XT_WORDS + WS_WORDS) * 4 + 256)   // 57728

__device__ __forceinline__ void mma_f16(float* d, const uint32_t* a, const uint32_t* b) {
    asm volatile(
        "mma.sync.aligned.m16n8k16.row.col.f32.f16.f16.f32 "
        "{%0,%1,%2,%3}, {%4,%5,%6,%7}, {%8,%9}, {%0,%1,%2,%3};"
        : "+f"(d[0]), "+f"(d[1]), "+f"(d[2]), "+f"(d[3])
        : "r"(a[0]), "r"(a[1]), "r"(a[2]), "r"(a[3]), "r"(b[0]), "r"(b[1]));
}
__device__ __forceinline__ void ldsm_x4(uint32_t* r, uint32_t saddr) {
    asm volatile("ldmatrix.sync.aligned.m8n8.x4.shared.b16 {%0,%1,%2,%3}, [%4];"
        : "=r"(r[0]), "=r"(r[1]), "=r"(r[2]), "=r"(r[3]) : "r"(saddr));
}
__device__ __forceinline__ uint32_t smem_u32(const void* p) {
    uint32_t a;
    asm("{ .reg .u64 t; cvta.to.shared.u64 t, %1; cvt.u32.u64 %0, t; }"
        : "=r"(a) : "l"(p));
    return a;
}
__device__ __forceinline__ uint32_t pack_h2(float lo, float hi) {
    __half2 h = __floats2half2_rn(lo, hi);
    return *reinterpret_cast<uint32_t*>(&h);
}

// Load one x-tile position (row,col) as 8 packed fp16x2 words (16 ci).
__device__ __forceinline__ void load_pos(const float* __restrict__ xn, int h0,
                                         int pidx, uint32_t* pr) {
    const int row = pidx / 66;
    const int col = pidx - row * 66;
    const int gr = h0 - 1 + row;
    const int gc = col - 1;
    if ((unsigned)gr < HH && (unsigned)gc < WW) {
        const float* src = xn + gr * WW + gc;
        #pragma unroll
        for (int j = 0; j < 8; j++)
            pr[j] = pack_h2(__ldg(src + (2 * j) * HWELEMS),
                            __ldg(src + (2 * j + 1) * HWELEMS));
    } else {
        #pragma unroll
        for (int j = 0; j < 8; j++) pr[j] = 0u;
    }
}
__device__ __forceinline__ void sts_pos(uint32_t* xtb, int pidx, const uint32_t* pr) {
    const int row = pidx / 66;
    const int col = pidx - row * 66;
    uint32_t* dst = xtb + row * XT_ROW_W + col * XT_COL_W;
    *(uint4*)(dst)     = make_uint4(pr[0], pr[1], pr[2], pr[3]);
    *(uint4*)(dst + 4) = make_uint4(pr[4], pr[5], pr[6], pr[7]);
}

// ---------------------------------------------------------------------------
// fp16 implicit-GEMM conv + in-register gate epilogue, software-pipelined,
// ldmatrix fragment feeds (A: x4 per (tap,mf); B: x4 per (tap, gate-pair)).
// CTA: 256 thr, tile M=256 px (4 rows x 64 w) x N=64 co (co-half q).
// Warps 4(m) x 2(n); warp N-tile = 4 gates x 8 chans -> gates fused in regs.
// ---------------------------------------------------------------------------
__global__ void __launch_bounds__(256, 2)
conv_gates_mma_kernel(const float* __restrict__ x,
                      const float* __restrict__ Wt,
                      const float* __restrict__ bias)
{
    extern __shared__ uint32_t smw[];
    uint32_t* xt0 = smw;
    uint32_t* xt1 = smw + XT_WORDS;
    uint32_t* ws  = smw + 2 * XT_WORDS;
    float*    bsp = (float*)(smw + 2 * XT_WORDS + WS_WORDS);

    const int tid  = threadIdx.x;
    const int lane = tid & 31;
    const int wid  = tid >> 5;
    const int gid  = lane >> 2;     // 0..7
    const int tig  = lane & 3;      // 0..3
    const int wm   = wid & 3;       // spatial row within 4-row tile
    const int wn   = wid >> 2;      // channel group (8 chans)

    const int q   = blockIdx.x & 1;    // co-half: hid chans q*16..q*16+15
    const int uid = blockIdx.x >> 1;   // 0..147

    // ---- stage weights as fp16 pairs: ws[lc][k], lc = g*16 + chan_local ----
    for (int i = tid; i < 64 * 72; i += 256) {
        int lc = i / 72, kw2 = i - lc * 72;
        int k0 = kw2 * 2;
        int cc = k0 >> 4, ci = k0 & 15;
        int co = ((lc >> 4) << 5) + (q << 4) + (lc & 15);
        float v0 = __ldg(&Wt[(co * 16 + ci)     * 9 + cc]);
        float v1 = __ldg(&Wt[(co * 16 + ci + 1) * 9 + cc]);
        ws[lc * WS_LC_W + kw2] = pack_h2(v0, v1);
    }
    if (tid < 64)
        bsp[tid] = bias[((tid >> 4) << 5) + (q << 4) + (tid & 15)];

    const int cl0 = wn * 8 + tig * 2;   // chan_local for even accum cols

    // ldmatrix per-lane address components (byte offsets)
    // A: matrices m0..m3 = (px0-7,k0-7),(px8-15,k0-7),(px0-7,k8-15),(px8-15,k8-15)
    const int pxr   = (lane & 7) + ((lane >> 3) & 1) * 8;   // px row within 16
    const int awoff = ((lane >> 4) & 1) * 4;                // +4 words for k8-15
    const uint32_t aoff = (uint32_t)(pxr * XT_COL_W + awoff) * 4;
    // B: m0,m1 = gate ga (k0-7 / k8-15), m2,m3 = gate ga+1
    const int bg    = (lane >> 4);                          // 0/1 -> gate offset
    const int bwoff = ((lane >> 3) & 1) * 4;
    const uint32_t boff = (uint32_t)(((bg << 4) + (wn << 3) + (lane & 7)) * WS_LC_W + bwoff) * 4;

    const uint32_t xt0_u = smem_u32(xt0);
    const uint32_t xt1_u = smem_u32(xt1);
    const uint32_t ws_u  = smem_u32(ws);

    // ---- prologue: load first tile into xt0 ----
    {
        const float* xn = x + (size_t)(uid >> 4) * CIN * HWELEMS;
        const int h0 = (uid & 15) << 2;
        uint32_t pr[8];
        load_pos(xn, h0, tid, pr);
        sts_pos(xt0, tid, pr);
        if (tid + 256 < 396) {
            load_pos(xn, h0, tid + 256, pr);
            sts_pos(xt0, tid + 256, pr);
        }
    }
    __syncthreads();

    int buf = 0;
    for (int u = uid; u < 2048; u += 148) {
        const int n  = u >> 4;
        const int h0 = (u & 15) << 2;
        const int un = u + 148;
        const bool nx = (un < 2048);

        // ---- issue next-tile loads into registers (hidden under MMA) ----
        uint32_t pr0[8], pr1[8];
        if (nx) {
            const float* xn2 = x + (size_t)(un >> 4) * CIN * HWELEMS;
            const int h02 = (un & 15) << 2;
            load_pos(xn2, h02, tid, pr0);
            if (tid + 256 < 396) load_pos(xn2, h02, tid + 256, pr1);
        }

        const uint32_t xb_u = buf ? xt1_u : xt0_u;
        uint32_t* xnb       = buf ? xt0 : xt1;

        // ---- GEMM mainloop: 9 taps, k16 per tap ----
        float acc[4][4][4];   // [mf][gate][frag]
        #pragma unroll
        for (int mf = 0; mf < 4; mf++)
            #pragma unroll
            for (int g = 0; g < 4; g++)
                #pragma unroll
                for (int e = 0; e < 4; e++) acc[mf][g][e] = 0.0f;

        #pragma unroll
        for (int cc = 0; cc < 9; cc++) {
            const int kh = cc / 3;
            const int kw = cc - kh * 3;
            // B frags: two ldmatrix.x4 -> gates 0,1 and 2,3
            uint32_t bf[4][2];
            {
                const uint32_t bbase = ws_u + boff + (uint32_t)(cc << 5);  // (cc*8 words)*4B
                uint32_t r01[4], r23[4];
                ldsm_x4(r01, bbase);
                ldsm_x4(r23, bbase + 32u * WS_LC_W * 4u);
                bf[0][0] = r01[0]; bf[0][1] = r01[1];
                bf[1][0] = r01[2]; bf[1][1] = r01[3];
                bf[2][0] = r23[0]; bf[2][1] = r23[1];
                bf[3][0] = r23[2]; bf[3][1] = r23[3];
            }
            const uint32_t abase = xb_u + aoff
                + (uint32_t)((wm + kh) * XT_ROW_W + kw * XT_COL_W) * 4;
            #pragma unroll
            for (int mf = 0; mf < 4; mf++) {
                uint32_t af[4];
                ldsm_x4(af, abase + (uint32_t)(mf * 16 * XT_COL_W) * 4);
                #pragma unroll
                for (int g = 0; g < 4; g++)
                    mma_f16(acc[mf][g], af, bf[g]);
            }
        }

        // ---- store next tile to back buffer (frees pipeline regs) ----
        if (nx) {
            sts_pos(xnb, tid, pr0);
            if (tid + 256 < 396) sts_pos(xnb, tid + 256, pr1);
        }

        // ---- in-register gate epilogue -> fp16 scratch planes ----
        const int h = h0 + wm;
        const float bI0 = bsp[cl0],      bI1 = bsp[cl0 + 1];
        const float bF0 = bsp[16 + cl0], bF1 = bsp[16 + cl0 + 1];
        const float bO0 = bsp[32 + cl0], bO1 = bsp[32 + cl0 + 1];
        const float bC0 = bsp[48 + cl0], bC1 = bsp[48 + cl0 + 1];
        #pragma unroll
        for (int mf = 0; mf < 4; mf++) {
            #pragma unroll
            for (int eh = 0; eh < 2; eh++) {
                const int w = mf * 16 + gid + eh * 8;
                #pragma unroll
                for (int ec = 0; ec < 2; ec++) {
                    const int e = eh * 2 + ec;
                    float iv = acc[mf][0][e] + (ec ? bI1 : bI0);
                    float fv = acc[mf][1][e] + (ec ? bF1 : bF0);
                    float ov = acc[mf][2][e] + (ec ? bO1 : bO0);
                    float cv = acc[mf][3][e] + (ec ? bC1 : bC0);
                    float ei  = __expf(-iv);
                    float ef  = __expf(-fv);
                    float inv = __fdividef(1.f, 2.f + ei + ef);
                    float fp  = (1.f + ei) * inv;                   // f'
                    float ip  = 1.f - fp;                           // i' (exact: f'+i'=1)
                    float g   = (cv >= 0.f) ? (cv + 0.5f)
                              : __fdividef(1.f, 1.f + __expf(-cv));
                    float so  = __fdividef(1.f, 1.f + __expf(-ov));
                    const int chan = (q << 4) + cl0 + ec;
                    size_t idx = ((size_t)n * HID + chan) * HWELEMS
                                 + (size_t)h * WW + w;
                    scA[idx] = pack_h2(fp, ip * g);
                    scB[idx] = __float2half_rn(so);
                }
            }
        }

        __syncthreads();   // STS to back buffer visible before next MMA
        buf ^= 1;
    }
}

// ---------------------------------------------------------------------------
// Scan: streaming recurrence on fp16 gate planes, 2 sequences per thread.
// At the DRAM byte wall (168 MB) — do not touch.
// ---------------------------------------------------------------------------
__global__ void __launch_bounds__(256)
lstm_scan_kernel(const float* __restrict__ c0,
                 float* __restrict__ out,
                 float* __restrict__ clast)
{
    const int t  = blockIdx.x * blockDim.x + threadIdx.x;   // 0..131071
    const int hw = (t & 2047) << 1;
    const int ch = (t >> 11) & 31;
    const int b  = t >> 16;

    float2 cs = *(const float2*)&c0[((size_t)b * HID + ch) * HWELEMS + hw];
    const size_t ST = (size_t)HID * HWELEMS;     // per-timestep stride
    size_t idx = ((size_t)(b * SS) * HID + ch) * HWELEMS + hw;
    const uint32_t* pA = scA + idx;
    const __half*   pB = scB + idx;
    float* op = out + idx;

    #pragma unroll 4
    for (int s = 0; s < SS; s++) {
        uint2 a = *(const uint2*)pA;
        __half2 sb = *(const __half2*)pB;
        float2 v0 = __half22float2(*reinterpret_cast<__half2*>(&a.x)); // (f', ig)
        float2 v1 = __half22float2(*reinterpret_cast<__half2*>(&a.y));
        float2 so = __half22float2(sb);
        cs.x = fmaf(v0.x, cs.x, v0.y);
        cs.y = fmaf(v1.x, cs.y, v1.y);
        *(float2*)op = make_float2(so.x * cs.x, so.y * cs.y);
        pA += ST;
        pB += ST;
        op += ST;
    }
    *(float2*)&clast[((size_t)b * HID + ch) * HWELEMS + hw] = cs;
}

// ---------------------------------------------------------------------------
extern "C" void kernel_launch(void* const* d_in, const int* in_sizes, int n_in,
                              void* d_out, int out_size)
{
    const float* x  = (const float*)d_in[0];   // (2,64,16,64,64)
    const float* Wt = (const float*)d_in[1];   // (128,16,3,3)
    const float* b  = (const float*)d_in[2];   // (128)
    const float* c0 = (const float*)d_in[3];   // (2,1,32,64,64)

    float* out   = (float*)d_out;                              // (2,64,32,64,64)
    float* clast = out + (size_t)BB * SS * HID * HWELEMS;      // (2,1,32,64,64)

    cudaFuncSetAttribute(conv_gates_mma_kernel,
                         cudaFuncAttributeMaxDynamicSharedMemorySize, SMEM_DYN);

    conv_gates_mma_kernel<<<296, 256, SMEM_DYN>>>(x, Wt, b);

    const int total2 = BB * HID * HWELEMS / 2;   // 131072
    lstm_scan_kernel<<<total2 / 256, 256>>>(c0, out, clast);
}